// round 5
// baseline (speedup 1.0000x reference)
#include <cuda_runtime.h>
#include <cuda_bf16.h>
#include <mma.h>
#include <math.h>
#include <stdint.h>

using namespace nvcuda;

#define B_ 4
#define C_ 96
#define H_ 256
#define W_ 256
#define HW (H_*W_)
#define LDA 104
#define LDB 136

typedef uint32_t u32;

// Scratch (allocation-free rule: __device__ globals)
__device__ float g_xn[B_*C_*HW];   // layernorm output
__device__ float g_buf[B_*C_*HW];  // e0_pre, later x1
__device__ float g_xa[B_*C_*HW];  // x_adaptive

// Pre-split bf16 weights (hi/lo), padded row-major [rows][LDA]
__device__ __align__(16) __nv_bfloat16 g_e0h[96*LDA], g_e0l[96*LDA];
__device__ __align__(16) __nv_bfloat16 g_pjh[96*LDA], g_pjl[96*LDA];
__device__ __align__(16) __nv_bfloat16 g_w1h[2*96*LDA], g_w1l[2*96*LDA]; // chunk oc: w1 rows [oc*96,+96)
__device__ __align__(16) __nv_bfloat16 g_w2h[2*96*LDA], g_w2l[2*96*LDA]; // chunk kc: w2 cols [kc*96,+96)

__device__ __forceinline__ void split_bf16(float v, __nv_bfloat16& h, __nv_bfloat16& l) {
    h = __float2bfloat16_rn(v);
    l = __float2bfloat16_rn(v - __bfloat162float(h));
}

using FragA = wmma::fragment<wmma::matrix_a, 16, 16, 16, __nv_bfloat16, wmma::row_major>;
using FragB = wmma::fragment<wmma::matrix_b, 16, 16, 16, __nv_bfloat16, wmma::row_major>;
using FragC = wmma::fragment<wmma::accumulator, 16, 16, 16, float>;

// C[96 x 128] += A[96 x 96] * B[96 x 128], 3-term bf16 split.
// Warp (wm in 0..1, wn in 0..3) owns rows wm*48..+48, cols wn*32..+32.
__device__ __forceinline__ void gemm3_96(
    const __nv_bfloat16* ah, const __nv_bfloat16* al,
    const __nv_bfloat16* bh, const __nv_bfloat16* bl,
    FragC (&acc)[3][2], int wm, int wn)
{
    #pragma unroll 1
    for (int k = 0; k < 6; k++) {
        FragB b_h[2], b_l[2];
        #pragma unroll
        for (int nf = 0; nf < 2; nf++) {
            const int c0 = wn * 32 + nf * 16;
            wmma::load_matrix_sync(b_h[nf], bh + (k * 16) * LDB + c0, LDB);
            wmma::load_matrix_sync(b_l[nf], bl + (k * 16) * LDB + c0, LDB);
        }
        #pragma unroll
        for (int mf = 0; mf < 3; mf++) {
            const int m0 = wm * 48 + mf * 16;
            FragA a_h, a_l;
            wmma::load_matrix_sync(a_h, ah + m0 * LDA + k * 16, LDA);
            wmma::load_matrix_sync(a_l, al + m0 * LDA + k * 16, LDA);
            #pragma unroll
            for (int nf = 0; nf < 2; nf++) {
                wmma::mma_sync(acc[mf][nf], a_h, b_h[nf], acc[mf][nf]);
                wmma::mma_sync(acc[mf][nf], a_h, b_l[nf], acc[mf][nf]);
                wmma::mma_sync(acc[mf][nf], a_l, b_h[nf], acc[mf][nf]);
            }
        }
    }
}

// ---------------------------------------------------------------------------
// Weight prep: f32 -> bf16 hi/lo, padded layouts
// ---------------------------------------------------------------------------
__global__ void k_prep(const float* __restrict__ e0, const float* __restrict__ pj,
                       const float* __restrict__ w1, const float* __restrict__ w2)
{
    int i = blockIdx.x * 256 + threadIdx.x;
    float v; __nv_bfloat16 *dh, *dl; int off;
    if (i < 9216) {
        int m = i / 96, k = i % 96;
        v = e0[i]; dh = g_e0h; dl = g_e0l; off = m * LDA + k;
    } else if (i < 18432) {
        int j = i - 9216; int m = j / 96, k = j % 96;
        v = pj[j]; dh = g_pjh; dl = g_pjl; off = m * LDA + k;
    } else if (i < 36864) {
        int j = i - 18432; int m = j / 96, k = j % 96;   // m 0..191
        v = w1[j]; dh = g_w1h; dl = g_w1l;
        off = (m / 96) * 96 * LDA + (m % 96) * LDA + k;
    } else if (i < 55296) {
        int j = i - 36864; int m = j / 192, k = j % 192; // w2 [96][192]
        v = w2[j]; dh = g_w2h; dl = g_w2l;
        off = (k / 96) * 96 * LDA + m * LDA + (k % 96);
    } else return;
    __nv_bfloat16 h, l; split_bf16(v, h, l);
    dh[off] = h; dl[off] = l;
}

// ---------------------------------------------------------------------------
// Kernel 1: LayerNorm (writes g_xn) + e0 pointwise via WMMA -> g_buf
// ---------------------------------------------------------------------------
#define LN_XS    0
#define LN_XSH   49152
#define LN_XSL   75264
#define LN_WSH   101376
#define LN_WSL   121344
#define LN_STG   141312
#define LN_MU    149504
#define LN_INV   150016
#define LN_LNW   150528
#define LN_LNB   150912
#define LN_BS    151296
#define LN_SMEM  151680

__global__ __launch_bounds__(256, 1) void k_ln_e0pw(
    const float* __restrict__ x,
    const float* __restrict__ lnw, const float* __restrict__ lnb,
    const float* __restrict__ bias)
{
    extern __shared__ unsigned char smraw[];
    float* xs  = (float*)(smraw + LN_XS);
    __nv_bfloat16* xsh = (__nv_bfloat16*)(smraw + LN_XSH);
    __nv_bfloat16* xsl = (__nv_bfloat16*)(smraw + LN_XSL);
    __nv_bfloat16* wsh = (__nv_bfloat16*)(smraw + LN_WSH);
    __nv_bfloat16* wsl = (__nv_bfloat16*)(smraw + LN_WSL);
    float* stage = (float*)(smraw + LN_STG);
    float* mu   = (float*)(smraw + LN_MU);
    float* inv  = (float*)(smraw + LN_INV);
    float* lnws = (float*)(smraw + LN_LNW);
    float* lnbs = (float*)(smraw + LN_LNB);
    float* bs   = (float*)(smraw + LN_BS);

    const int t = threadIdx.x, wid = t >> 5, lane = t & 31;
    const int b = blockIdx.y;
    const int p0 = blockIdx.x * 128;
    const float* xb = x + (size_t)b * C_ * HW + p0;

    for (int i = t; i < 96 * 32; i += 256) {
        int k = i >> 5, c4 = i & 31;
        ((float4*)(xs + k * 128))[c4] = ((const float4*)(xb + (size_t)k * HW))[c4];
    }
    for (int i = t; i < 1248; i += 256) {
        ((float4*)wsh)[i] = ((const float4*)g_e0h)[i];
        ((float4*)wsl)[i] = ((const float4*)g_e0l)[i];
    }
    if (t < 96) { lnws[t] = lnw[t]; lnbs[t] = lnb[t]; bs[t] = bias[t]; }
    __syncthreads();

    if (t < 128) {
        float s = 0.f, s2 = 0.f;
        #pragma unroll 8
        for (int k = 0; k < 96; k++) {
            float v = xs[k * 128 + t];
            s += v; s2 += v * v;
        }
        float m = s * (1.f / 96.f);
        float var = s2 * (1.f / 96.f) - m * m;
        mu[t] = m;
        inv[t] = rsqrtf(var + 1e-6f);
    }
    __syncthreads();

    float* xnb = g_xn + (size_t)b * C_ * HW + p0;
    for (int i = t; i < 12288; i += 256) {
        int k = i >> 7, p = i & 127;
        float v = (xs[i] - mu[p]) * inv[p] * lnws[k] + lnbs[k];
        xnb[(size_t)k * HW + p] = v;
        __nv_bfloat16 h, l; split_bf16(v, h, l);
        xsh[k * LDB + p] = h;
        xsl[k * LDB + p] = l;
    }
    __syncthreads();

    const int wm = wid >> 2, wn = wid & 3;
    FragC acc[3][2];
    #pragma unroll
    for (int mf = 0; mf < 3; mf++)
        #pragma unroll
        for (int nf = 0; nf < 2; nf++) wmma::fill_fragment(acc[mf][nf], 0.f);
    gemm3_96(wsh, wsl, xsh, xsl, acc, wm, wn);

    float* st = stage + wid * 256;
    float* gb = g_buf + (size_t)b * C_ * HW + p0;
    const int r = lane >> 1, cc = (lane & 1) * 8;
    #pragma unroll
    for (int mf = 0; mf < 3; mf++)
        #pragma unroll
        for (int nf = 0; nf < 2; nf++) {
            wmma::store_matrix_sync(st, acc[mf][nf], 16, wmma::mem_row_major);
            __syncwarp();
            int mm = wm * 48 + mf * 16 + r;
            int pp = wn * 32 + nf * 16 + cc;
            float bb = bs[mm];
            float* gp = gb + (size_t)mm * HW + pp;
            const float* sp = st + r * 16 + cc;
            #pragma unroll
            for (int q = 0; q < 8; q++) gp[q] = sp[q] + bb;
            __syncwarp();
        }
}

// ---------------------------------------------------------------------------
// Kernel 2: depthwise experts + mixing + prompt (unchanged scalar)
// ---------------------------------------------------------------------------
#define TS 32
__global__ __launch_bounds__(256) void k_dw(
    const float* __restrict__ sw,
    const float* __restrict__ prompt,
    const float* __restrict__ w0, const float* __restrict__ b0,
    const float* __restrict__ w1, const float* __restrict__ b1,
    const float* __restrict__ w2, const float* __restrict__ b2)
{
    __shared__ float xs[44 * 44];
    __shared__ float es[34 * 34];

    int c = blockIdx.y, b = blockIdx.z;
    int ty0 = (blockIdx.x / (W_/TS)) * TS;
    int tx0 = (blockIdx.x % (W_/TS)) * TS;
    const float* xn = g_xn  + ((size_t)(b * C_ + c)) * HW;
    const float* ep = g_buf + ((size_t)(b * C_ + c)) * HW;

    for (int i = threadIdx.x; i < 44*44; i += 256) {
        int yy = ty0 - 6 + i / 44, xx = tx0 - 6 + i % 44;
        xs[i] = (yy >= 0 && yy < H_ && xx >= 0 && xx < W_) ? xn[yy * W_ + xx] : 0.f;
    }
    for (int i = threadIdx.x; i < 34*34; i += 256) {
        int yy = ty0 - 1 + i / 34, xx = tx0 - 1 + i % 34;
        es[i] = (yy >= 0 && yy < H_ && xx >= 0 && xx < W_) ? ep[yy * W_ + xx] : 0.f;
    }

    float k0[9], k1[9], k2[25];
    #pragma unroll
    for (int i = 0; i < 9; i++)  { k0[i] = __ldg(&w0[c*9 + i]);  k1[i] = __ldg(&w1[c*9 + i]); }
    #pragma unroll
    for (int i = 0; i < 25; i++) k2[i] = __ldg(&w2[c*25 + i]);
    float bb0 = __ldg(&b0[c]), bb1 = __ldg(&b1[c]), bb2 = __ldg(&b2[c]);
    float s0 = __ldg(&sw[b*3 + 0]), s1 = __ldg(&sw[b*3 + 1]), s2 = __ldg(&sw[b*3 + 2]);
    float pm = 1.f + __ldg(&prompt[b * C_ + c]);
    __syncthreads();

    float* outp = g_xa + ((size_t)(b * C_ + c)) * HW;
    #pragma unroll
    for (int k = 0; k < 4; k++) {
        int li = threadIdx.x + k * 256;
        int py = li / TS, px = li % TS;
        float e0v = bb0;
        #pragma unroll
        for (int ky = 0; ky < 3; ky++)
            #pragma unroll
            for (int kx = 0; kx < 3; kx++)
                e0v += k0[ky*3 + kx] * es[(py + ky) * 34 + (px + kx)];
        float e1v = bb1;
        #pragma unroll
        for (int ky = 0; ky < 3; ky++)
            #pragma unroll
            for (int kx = 0; kx < 3; kx++)
                e1v += k1[ky*3 + kx] * xs[(py + 4 + 2*ky) * 44 + (px + 4 + 2*kx)];
        float e2v = bb2;
        #pragma unroll
        for (int ky = 0; ky < 5; ky++)
            #pragma unroll
            for (int kx = 0; kx < 5; kx++)
                e2v += k2[ky*5 + kx] * xs[(py + 3*ky) * 44 + (px + 3*kx)];
        outp[(ty0 + py) * W_ + (tx0 + px)] = (s0*e0v + s1*e1v + s2*e2v) * pm;
    }
}

// ---------------------------------------------------------------------------
// Kernel 3: x1 = x + proj(x_adaptive) via WMMA -> g_buf
// ---------------------------------------------------------------------------
#define PJ_XSH   0
#define PJ_XSL   26112
#define PJ_WSH   52224
#define PJ_WSL   72192
#define PJ_STG   92160
#define PJ_BS    100352
#define PJ_SMEM  100736

__global__ __launch_bounds__(256, 2) void k_proj(
    const float* __restrict__ x, const float* __restrict__ bias)
{
    extern __shared__ unsigned char smraw[];
    __nv_bfloat16* xsh = (__nv_bfloat16*)(smraw + PJ_XSH);
    __nv_bfloat16* xsl = (__nv_bfloat16*)(smraw + PJ_XSL);
    __nv_bfloat16* wsh = (__nv_bfloat16*)(smraw + PJ_WSH);
    __nv_bfloat16* wsl = (__nv_bfloat16*)(smraw + PJ_WSL);
    float* stage = (float*)(smraw + PJ_STG);
    float* bs    = (float*)(smraw + PJ_BS);

    const int t = threadIdx.x, wid = t >> 5, lane = t & 31;
    const int b = blockIdx.y;
    const int p0 = blockIdx.x * 128;
    const float* ab = g_xa + (size_t)b * C_ * HW + p0;

    for (int i = t; i < 96 * 32; i += 256) {
        int k = i >> 5, c4 = (i & 31) * 4;
        float4 v = *(const float4*)(ab + (size_t)k * HW + c4);
        __nv_bfloat16 h0,l0,h1,l1,h2,l2,h3,l3;
        split_bf16(v.x, h0, l0); split_bf16(v.y, h1, l1);
        split_bf16(v.z, h2, l2); split_bf16(v.w, h3, l3);
        __nv_bfloat162* ph = (__nv_bfloat162*)(xsh + k * LDB + c4);
        __nv_bfloat162* pl = (__nv_bfloat162*)(xsl + k * LDB + c4);
        ph[0] = __nv_bfloat162{h0, h1}; ph[1] = __nv_bfloat162{h2, h3};
        pl[0] = __nv_bfloat162{l0, l1}; pl[1] = __nv_bfloat162{l2, l3};
    }
    for (int i = t; i < 1248; i += 256) {
        ((float4*)wsh)[i] = ((const float4*)g_pjh)[i];
        ((float4*)wsl)[i] = ((const float4*)g_pjl)[i];
    }
    if (t < 96) bs[t] = bias[t];
    __syncthreads();

    const int wm = wid >> 2, wn = wid & 3;
    FragC acc[3][2];
    #pragma unroll
    for (int mf = 0; mf < 3; mf++)
        #pragma unroll
        for (int nf = 0; nf < 2; nf++) wmma::fill_fragment(acc[mf][nf], 0.f);
    gemm3_96(wsh, wsl, xsh, xsl, acc, wm, wn);

    float* st = stage + wid * 256;
    const float* rb = x + (size_t)b * C_ * HW + p0;
    float* gb = g_buf + (size_t)b * C_ * HW + p0;
    const int r = lane >> 1, cc = (lane & 1) * 8;
    #pragma unroll
    for (int mf = 0; mf < 3; mf++)
        #pragma unroll
        for (int nf = 0; nf < 2; nf++) {
            wmma::store_matrix_sync(st, acc[mf][nf], 16, wmma::mem_row_major);
            __syncwarp();
            int mm = wm * 48 + mf * 16 + r;
            int pp = wn * 32 + nf * 16 + cc;
            float bb = bs[mm];
            float* gp = gb + (size_t)mm * HW + pp;
            const float* rp = rb + (size_t)mm * HW + pp;
            const float* sp = st + r * 16 + cc;
            #pragma unroll
            for (int q = 0; q < 8; q++) gp[q] = sp[q] + bb + rp[q];
            __syncwarp();
        }
}

// ---------------------------------------------------------------------------
// Kernel 4: out = x1 + ffn2(gelu(ffn1(x1))) via WMMA; h in SMEM (bf16 hi/lo)
// ---------------------------------------------------------------------------
#define FF_XSH   0
#define FF_XSL   26112
#define FF_HSH   52224
#define FF_HSL   104448
#define FF_WSH   156672
#define FF_WSL   176640
#define FF_STG   196608
#define FF_B1S   204800
#define FF_B2S   205568
#define FF_SMEM  205952

__global__ __launch_bounds__(256, 1) void k_ffn(
    const float* __restrict__ b1v, const float* __restrict__ b2v,
    float* __restrict__ out)
{
    extern __shared__ unsigned char smraw[];
    __nv_bfloat16* xsh = (__nv_bfloat16*)(smraw + FF_XSH);
    __nv_bfloat16* xsl = (__nv_bfloat16*)(smraw + FF_XSL);
    __nv_bfloat16* hsh = (__nv_bfloat16*)(smraw + FF_HSH);
    __nv_bfloat16* hsl = (__nv_bfloat16*)(smraw + FF_HSL);
    __nv_bfloat16* wsh = (__nv_bfloat16*)(smraw + FF_WSH);
    __nv_bfloat16* wsl = (__nv_bfloat16*)(smraw + FF_WSL);
    float* stage = (float*)(smraw + FF_STG);
    float* b1s   = (float*)(smraw + FF_B1S);
    float* b2s   = (float*)(smraw + FF_B2S);

    const int t = threadIdx.x, wid = t >> 5, lane = t & 31;
    const int b = blockIdx.y;
    const int p0 = blockIdx.x * 128;
    const float* x1g = g_buf + (size_t)b * C_ * HW + p0;

    for (int i = t; i < 96 * 32; i += 256) {
        int k = i >> 5, c4 = (i & 31) * 4;
        float4 v = *(const float4*)(x1g + (size_t)k * HW + c4);
        __nv_bfloat16 h0,l0,h1,l1,h2,l2,h3,l3;
        split_bf16(v.x, h0, l0); split_bf16(v.y, h1, l1);
        split_bf16(v.z, h2, l2); split_bf16(v.w, h3, l3);
        __nv_bfloat162* ph = (__nv_bfloat162*)(xsh + k * LDB + c4);
        __nv_bfloat162* pl = (__nv_bfloat162*)(xsl + k * LDB + c4);
        ph[0] = __nv_bfloat162{h0, h1}; ph[1] = __nv_bfloat162{h2, h3};
        pl[0] = __nv_bfloat162{l0, l1}; pl[1] = __nv_bfloat162{l2, l3};
    }
    if (t < 192) b1s[t] = b1v[t];
    if (t < 96)  b2s[t] = b2v[t];

    const int wm = wid >> 2, wn = wid & 3;
    const int r = lane >> 1, cc = (lane & 1) * 8;
    float* st = stage + wid * 256;

    // ---- GEMM1: h = gelu(w1 @ x1 + b1), two 96-row chunks ----
    #pragma unroll 1
    for (int oc = 0; oc < 2; oc++) {
        __syncthreads();   // xs ready (oc=0); prior ws readers done (oc=1)
        for (int i = t; i < 1248; i += 256) {
            ((float4*)wsh)[i] = ((const float4*)(g_w1h + oc * 96 * LDA))[i];
            ((float4*)wsl)[i] = ((const float4*)(g_w1l + oc * 96 * LDA))[i];
        }
        __syncthreads();

        FragC acc[3][2];
        #pragma unroll
        for (int mf = 0; mf < 3; mf++)
            #pragma unroll
            for (int nf = 0; nf < 2; nf++) wmma::fill_fragment(acc[mf][nf], 0.f);
        gemm3_96(wsh, wsl, xsh, xsl, acc, wm, wn);

        #pragma unroll
        for (int mf = 0; mf < 3; mf++)
            #pragma unroll
            for (int nf = 0; nf < 2; nf++) {
                wmma::store_matrix_sync(st, acc[mf][nf], 16, wmma::mem_row_major);
                __syncwarp();
                int k2 = oc * 96 + wm * 48 + mf * 16 + r;
                int pp = wn * 32 + nf * 16 + cc;
                float bb = b1s[k2];
                const float* sp = st + r * 16 + cc;
                #pragma unroll
                for (int q = 0; q < 8; q++) {
                    float hv = sp[q] + bb;
                    float gv = hv * normcdff(hv);
                    __nv_bfloat16 hh, ll; split_bf16(gv, hh, ll);
                    hsh[k2 * LDB + pp + q] = hh;
                    hsl[k2 * LDB + pp + q] = ll;
                }
                __syncwarp();
            }
    }

    // ---- GEMM2: out = x1 + w2 @ h + b2, K=192 in two chunks ----
    FragC acc2[3][2];
    #pragma unroll
    for (int mf = 0; mf < 3; mf++)
        #pragma unroll
        for (int nf = 0; nf < 2; nf++) wmma::fill_fragment(acc2[mf][nf], 0.f);

    #pragma unroll 1
    for (int kc = 0; kc < 2; kc++) {
        __syncthreads();   // hs complete / prior ws readers done
        for (int i = t; i < 1248; i += 256) {
            ((float4*)wsh)[i] = ((const float4*)(g_w2h + kc * 96 * LDA))[i];
            ((float4*)wsl)[i] = ((const float4*)(g_w2l + kc * 96 * LDA))[i];
        }
        __syncthreads();
        gemm3_96(wsh, wsl, hsh + kc * 96 * LDB, hsl + kc * 96 * LDB, acc2, wm, wn);
    }

    float* ob = out + (size_t)b * C_ * HW + p0;
    #pragma unroll
    for (int mf = 0; mf < 3; mf++)
        #pragma unroll
        for (int nf = 0; nf < 2; nf++) {
            wmma::store_matrix_sync(st, acc2[mf][nf], 16, wmma::mem_row_major);
            __syncwarp();
            int mm = wm * 48 + mf * 16 + r;
            int pp = wn * 32 + nf * 16 + cc;
            float bb = b2s[mm];
            const float* sp = st + r * 16 + cc;
            const float* rp = x1g + (size_t)mm * HW + pp;
            float* gp = ob + (size_t)mm * HW + pp;
            #pragma unroll
            for (int q = 0; q < 8; q++) gp[q] = sp[q] + bb + rp[q];
            __syncwarp();
        }
}

// ---------------------------------------------------------------------------
extern "C" void kernel_launch(void* const* d_in, const int* in_sizes, int n_in,
                              void* d_out, int out_size)
{
    const float* x       = (const float*)d_in[0];
    const float* prompt  = (const float*)d_in[1];
    const float* sweights= (const float*)d_in[2];
    const float* ln_w    = (const float*)d_in[3];
    const float* ln_b    = (const float*)d_in[4];
    const float* e0_pw_w = (const float*)d_in[5];
    const float* e0_pw_b = (const float*)d_in[6];
    const float* e0_dw_w = (const float*)d_in[7];
    const float* e0_dw_b = (const float*)d_in[8];
    const float* e1_dw_w = (const float*)d_in[9];
    const float* e1_dw_b = (const float*)d_in[10];
    const float* e2_dw_w = (const float*)d_in[11];
    const float* e2_dw_b = (const float*)d_in[12];
    const float* proj_w  = (const float*)d_in[13];
    const float* proj_b  = (const float*)d_in[14];
    const float* ffn1_w  = (const float*)d_in[15];
    const float* ffn1_b  = (const float*)d_in[16];
    const float* ffn2_w  = (const float*)d_in[17];
    const float* ffn2_b  = (const float*)d_in[18];
    float* out = (float*)d_out;

    cudaFuncSetAttribute(k_ln_e0pw, cudaFuncAttributeMaxDynamicSharedMemorySize, LN_SMEM);
    cudaFuncSetAttribute(k_proj,    cudaFuncAttributeMaxDynamicSharedMemorySize, PJ_SMEM);
    cudaFuncSetAttribute(k_ffn,     cudaFuncAttributeMaxDynamicSharedMemorySize, FF_SMEM);

    dim3 gg(HW / 128, B_);

    k_prep<<<216, 256>>>(e0_pw_w, proj_w, ffn1_w, ffn2_w);

    k_ln_e0pw<<<gg, 256, LN_SMEM>>>(x, ln_w, ln_b, e0_pw_b);

    dim3 gdw((H_/TS) * (W_/TS), C_, B_);
    k_dw<<<gdw, 256>>>(sweights, prompt,
                       e0_dw_w, e0_dw_b, e1_dw_w, e1_dw_b, e2_dw_w, e2_dw_b);

    k_proj<<<gg, 256, PJ_SMEM>>>(x, proj_b);

    k_ffn<<<gg, 256, FF_SMEM>>>(ffn1_b, ffn2_b, out);
}